// round 11
// baseline (speedup 1.0000x reference)
#include <cuda_runtime.h>
#include <math.h>

// x:       [B=8,  CI=32, 64,64,64] fp32   (bi = b*32+ci, 256)
// weights: [CI=32, CO=32, 16,16,16] fp32
// out:     [B=8,  CO=32, 64,64,64] fp32
// Orthonormal DCT-II truncated to 16 modes/axis.
// Symmetry: C[k][63-n] = (-1)^k C[k][n]  -> even/odd fold halves FLOPs.
//
// Pipeline (small intermediates only):
//   K1 : per (bi, y-pair): contract X (fold) + z (fold) in-block
//        -> t1E/t1O[bi][yp][kx][kz]   (256MB read -> 2x8.4MB write)
//   K2 : contract y (fold) -> g_modes[bi][kx,ky,kz]  (16.8MB -> 4MB)
//   K3 : channel mix
//   K45: fused full inverse, writes 256MB

#define S 64
#define M 16
#define BC 256
#define YZ 4096
#define MODES 4096

__device__ float g_C[M * S];                      // C[k][n]
__device__ float g_t1E[(size_t)BC * 32 * 256];    // 8.4 MB
__device__ float g_t1O[(size_t)BC * 32 * 256];    // 8.4 MB
__device__ float g_modes[(size_t)BC * MODES];     // 4.2 MB
__device__ float g_mixed[(size_t)BC * MODES];     // 4.2 MB

// ---------------- init --------------------------------------------------
__global__ void k0_init() {
    int t = threadIdx.x;            // 0..1023
    int k = t >> 6, n = t & 63;
    double v = sqrt(2.0 / (double)S) * cos(M_PI * ((double)n + 0.5) * (double)k / (double)S);
    if (k == 0) v *= 1.0 / sqrt(2.0);
    g_C[t] = (float)v;
}

// folded table sC[k*32 + n'] = C[k][n'], n' < 32
__device__ __forceinline__ void load_Cfold(float* sC, int t) {
    for (int i = t; i < M * 32; i += 256)
        sC[i] = g_C[(i >> 5) * S + (i & 31)];
}

// ---------------- K1: fused forward X+z contraction, per (bi, yp) -------
// grid 8192 = 256 bi x 32 yp. Handles y = yp and y = 63-yp.
// out: t1E/t1O[(bi*32+yp)*256 + kx*16 + kz]
__global__ void __launch_bounds__(256) k1_fwd(const float* __restrict__ x) {
    __shared__ float sA[S * S];     // 16 KB slab at y=yp     [X][z]
    __shared__ float sB[S * S];     // 16 KB slab at y=63-yp
    __shared__ float t2A[M * S];    // 4 KB  [kx][z]
    __shared__ float t2B[M * S];    // 4 KB
    __shared__ float sC[M * 32];    // 2 KB

    const int t = threadIdx.x;
    const int bi = blockIdx.x >> 5;
    const int yp = blockIdx.x & 31;

    load_Cfold(sC, t);
    const float* base = x + (size_t)bi * (S * YZ);
    // load both slabs: 1024 float4 each; row = X (256 B contiguous per X)
    #pragma unroll
    for (int i = t; i < 1024; i += 256) {
        int X = i >> 4, c = i & 15;
        ((float4*)sA)[X * 16 + c] = *(const float4*)(base + (size_t)X * YZ + yp * S + c * 4);
        ((float4*)sB)[X * 16 + c] = *(const float4*)(base + (size_t)X * YZ + (63 - yp) * S + c * 4);
    }
    __syncthreads();

    // X contraction (fold): thread = (z = t&63, kxo = t>>6), kx = 4*kxo + j
    {
        const int z = t & 63, kxo = t >> 6;
        float a0 = 0.f, a1 = 0.f, a2 = 0.f, a3 = 0.f;
        float b0 = 0.f, b1 = 0.f, b2 = 0.f, b3 = 0.f;
        #pragma unroll 8
        for (int Xp = 0; Xp < 32; Xp++) {
            float aA = sA[Xp * S + z], bA = sA[(63 - Xp) * S + z];
            float eA = aA + bA, oA = aA - bA;
            float aB = sB[Xp * S + z], bB = sB[(63 - Xp) * S + z];
            float eB = aB + bB, oB = aB - bB;
            float c0 = sC[(4 * kxo + 0) * 32 + Xp];   // even kx -> e
            float c1 = sC[(4 * kxo + 1) * 32 + Xp];   // odd  kx -> o
            float c2 = sC[(4 * kxo + 2) * 32 + Xp];
            float c3 = sC[(4 * kxo + 3) * 32 + Xp];
            a0 += eA * c0; a1 += oA * c1; a2 += eA * c2; a3 += oA * c3;
            b0 += eB * c0; b1 += oB * c1; b2 += eB * c2; b3 += oB * c3;
        }
        t2A[(4 * kxo + 0) * S + z] = a0;
        t2A[(4 * kxo + 1) * S + z] = a1;
        t2A[(4 * kxo + 2) * S + z] = a2;
        t2A[(4 * kxo + 3) * S + z] = a3;
        t2B[(4 * kxo + 0) * S + z] = b0;
        t2B[(4 * kxo + 1) * S + z] = b1;
        t2B[(4 * kxo + 2) * S + z] = b2;
        t2B[(4 * kxo + 3) * S + z] = b3;
    }
    __syncthreads();

    // z contraction (fold): thread = (kx = t>>4, kz = t&15)
    {
        const int kx = t >> 4, kz = t & 15;
        const float* rA = &t2A[kx * S];
        const float* rB = &t2B[kx * S];
        const float* c = &sC[kz * 32];
        const float sgn = (kz & 1) ? -1.f : 1.f;
        float accA = 0.f, accB = 0.f;
        #pragma unroll 8
        for (int zp = 0; zp < 32; zp++) {
            accA += (rA[zp] + sgn * rA[63 - zp]) * c[zp];
            accB += (rB[zp] + sgn * rB[63 - zp]) * c[zp];
        }
        const size_t off = ((size_t)bi * 32 + yp) * 256 + t;
        g_t1E[off] = accA + accB;      // even-ky source
        g_t1O[off] = accA - accB;      // odd-ky source
    }
}

// ---------------- K2: contract y (fold), per bi -------------------------
// grid 256; thread = (kx,kz); modes[bi][kx*256 + ky*16 + kz]
__global__ void __launch_bounds__(256) k2_fwd_y() {
    __shared__ float sC[M * 32];
    const int t = threadIdx.x, bi = blockIdx.x;
    load_Cfold(sC, t);
    __syncthreads();

    const int kx = t >> 4, kz = t & 15;
    float accE[8], accO[8];
    #pragma unroll
    for (int j = 0; j < 8; j++) { accE[j] = 0.f; accO[j] = 0.f; }

    const float* pE = g_t1E + (size_t)bi * 32 * 256 + t;
    const float* pO = g_t1O + (size_t)bi * 32 * 256 + t;
    #pragma unroll 4
    for (int yp = 0; yp < 32; yp++) {
        float e = pE[yp * 256];
        float o = pO[yp * 256];
        #pragma unroll
        for (int j = 0; j < 8; j++) {
            accE[j] += e * sC[(2 * j) * 32 + yp];
            accO[j] += o * sC[(2 * j + 1) * 32 + yp];
        }
    }
    float* mp = g_modes + (size_t)bi * MODES + kx * 256 + kz;
    #pragma unroll
    for (int j = 0; j < 8; j++) {
        mp[(2 * j) * M] = accE[j];
        mp[(2 * j + 1) * M] = accO[j];
    }
}

// ---------------- K3: channel mix, batched register GEMM ----------------
__global__ void __launch_bounds__(256) k3_mix(const float* __restrict__ w) {
    __shared__ float s_m[8 * 32 * 16];   // [b][i][m] 16 KB
    __shared__ float s_w[32 * 16 * 16];  // [i][oo][m] 32 KB
    const int t = threadIdx.x;
    const int m0 = blockIdx.x * 16;
    const int o0 = blockIdx.y * 16;

    for (int idx = t; idx < 8 * 32 * 16; idx += 256) {
        int bi = idx >> 4, m = idx & 15;
        s_m[idx] = g_modes[(size_t)bi * MODES + m0 + m];
    }
    for (int idx = t; idx < 32 * 16 * 16; idx += 256) {
        int i = idx >> 8, oo = (idx >> 4) & 15, m = idx & 15;
        s_w[idx] = w[((size_t)i * 32 + o0 + oo) * MODES + m0 + m];
    }
    __syncthreads();

    const int oo = t >> 4;
    const int m = t & 15;
    float acc[8];
    #pragma unroll
    for (int b = 0; b < 8; b++) acc[b] = 0.f;
    #pragma unroll 8
    for (int i = 0; i < 32; i++) {
        float wv = s_w[(i * 16 + oo) * 16 + m];
        #pragma unroll
        for (int b = 0; b < 8; b++)
            acc[b] += s_m[(b * 32 + i) * 16 + m] * wv;
    }
    #pragma unroll
    for (int b = 0; b < 8; b++)
        g_mixed[((size_t)b * 32 + o0 + oo) * MODES + m0 + m] = acc[b];
}

// ---------------- K45: fused full inverse, per (bo, yp) -----------------
// Handles Y = yp and Y = 63-yp (y-fold). grid 8192 = 256 bo x 32 yp.
__global__ void __launch_bounds__(256) k45_inv(float* __restrict__ out) {
    __shared__ float s_m[MODES];     // 16 KB  [kx][ky][kz]
    __shared__ float sC[M * 32];     // 2 KB
    __shared__ float s_tA[256];      // [kx][kz] for Y=yp
    __shared__ float s_tB[256];      // [kx][kz] for Y=63-yp
    __shared__ float s_vA[M * S];    // 4 KB [kx][Z]
    __shared__ float s_vB[M * S];    // 4 KB

    const int t = threadIdx.x;
    const int bo = blockIdx.x >> 5;
    const int yp = blockIdx.x & 31;

    {   // load modes (float4)
        const float4* src = (const float4*)(g_mixed + (size_t)bo * MODES);
        float4* dst = (float4*)s_m;
        #pragma unroll
        for (int i = t; i < MODES / 4; i += 256) dst[i] = src[i];
    }
    load_Cfold(sC, t);
    __syncthreads();

    // stage1: expand ky -> Y (fold): tmp[kx][kz] for both Y rows
    {
        const int kx = t >> 4, kz = t & 15;
        float e = 0.f, o = 0.f;
        #pragma unroll
        for (int j = 0; j < 8; j++) {
            e += sC[(2 * j) * 32 + yp] * s_m[kx * 256 + (2 * j) * M + kz];
            o += sC[(2 * j + 1) * 32 + yp] * s_m[kx * 256 + (2 * j + 1) * M + kz];
        }
        s_tA[t] = e + o;      // Y = yp
        s_tB[t] = e - o;      // Y = 63 - yp
    }
    __syncthreads();

    // stage2: expand kz -> Z (fold): v[kx][Z], 512 (kx,zp) slots, 2/thread
    #pragma unroll
    for (int it = 0; it < 2; it++) {
        int sidx = t + 256 * it;
        int zp = sidx & 31, kx = sidx >> 5;
        float eA = 0.f, oA = 0.f, eB = 0.f, oB = 0.f;
        #pragma unroll
        for (int j = 0; j < 8; j++) {
            float cE = sC[(2 * j) * 32 + zp];
            float cO = sC[(2 * j + 1) * 32 + zp];
            eA += cE * s_tA[kx * M + 2 * j];
            oA += cO * s_tA[kx * M + 2 * j + 1];
            eB += cE * s_tB[kx * M + 2 * j];
            oB += cO * s_tB[kx * M + 2 * j + 1];
        }
        s_vA[kx * S + zp] = eA + oA;
        s_vA[kx * S + 63 - zp] = eA - oA;
        s_vB[kx * S + zp] = eB + oB;
        s_vB[kx * S + 63 - zp] = eB - oB;
    }
    __syncthreads();

    // stage3: expand kx -> X (fold), write float4.
    float* obase = out + (size_t)bo * (S * YZ);
    #pragma unroll
    for (int it = 0; it < 4; it++) {
        int s = t + 256 * it;
        int zq = s & 15;
        int Xp = (s >> 4) & 31;
        int var = s >> 9;
        const float* v = var ? s_vB : s_vA;
        const int Y = var ? (63 - yp) : yp;
        float4 e = make_float4(0.f, 0.f, 0.f, 0.f);
        float4 o = make_float4(0.f, 0.f, 0.f, 0.f);
        #pragma unroll
        for (int j = 0; j < 8; j++) {
            float cE = sC[(2 * j) * 32 + Xp];
            float cO = sC[(2 * j + 1) * 32 + Xp];
            float4 vE = *(const float4*)(v + (2 * j) * S + zq * 4);
            float4 vO = *(const float4*)(v + (2 * j + 1) * S + zq * 4);
            e.x += cE * vE.x; e.y += cE * vE.y; e.z += cE * vE.z; e.w += cE * vE.w;
            o.x += cO * vO.x; o.y += cO * vO.y; o.z += cO * vO.z; o.w += cO * vO.w;
        }
        float* r0 = obase + (size_t)Xp * YZ + Y * S + zq * 4;
        float* r1 = obase + (size_t)(63 - Xp) * YZ + Y * S + zq * 4;
        *(float4*)r0 = make_float4(e.x + o.x, e.y + o.y, e.z + o.z, e.w + o.w);
        *(float4*)r1 = make_float4(e.x - o.x, e.y - o.y, e.z - o.z, e.w - o.w);
    }
}

// ---------------- launch ------------------------------------------------
extern "C" void kernel_launch(void* const* d_in, const int* in_sizes, int n_in,
                              void* d_out, int out_size) {
    const float* x = (const float*)d_in[0];
    const float* w = (const float*)d_in[1];
    if (n_in >= 2 && in_sizes[0] == 32 * 32 * MODES) {   // defensive swap
        x = (const float*)d_in[1];
        w = (const float*)d_in[0];
    }
    float* out = (float*)d_out;

    k0_init<<<1, 1024>>>();
    k1_fwd<<<8192, 256>>>(x);
    k2_fwd_y<<<256, 256>>>();
    k3_mix<<<dim3(256, 2), 256>>>(w);
    k45_inv<<<8192, 256>>>(out);
}

// round 13
// speedup vs baseline: 1.1753x; 1.1753x over previous
#include <cuda_runtime.h>
#include <math.h>

// x:       [B=8,  CI=32, 64,64,64] fp32   (bi = b*32+ci, 256)
// weights: [CI=32, CO=32, 16,16,16] fp32
// out:     [B=8,  CO=32, 64,64,64] fp32
// Orthonormal DCT-II truncated to 16 modes/axis.
// Symmetry: C[k][63-n] = (-1)^k C[k][n]  -> even/odd fold halves FLOPs.
//
// Pipeline (R5 structure, fp32 throughout, register-cached K45 stage3):
//   K1 : g_big[bi][kx][yz]    = sum_X C[kx][X] x[bi][X][yz]  (256MB read, float4)
//   K2 : g_modes[bi][kx,ky,kz]= contract y,z                  (67MB -> 4MB)
//   K3 : g_mixed = channel mix
//   K45: out[bo][X][Y][Z]     = fused full inverse, writes 256MB

#define S 64
#define M 16
#define BC 256
#define YZ 4096
#define MODES 4096

__device__ float g_C[M * S];                     // C[k][n]
__device__ float g_big[(size_t)BC * M * YZ];     // 67 MB
__device__ float g_modes[(size_t)BC * MODES];    // 4.2 MB
__device__ float g_mixed[(size_t)BC * MODES];    // 4.2 MB

// ---------------- init --------------------------------------------------
__global__ void k0_init() {
    int t = threadIdx.x;            // 0..1023
    int k = t >> 6, n = t & 63;
    double v = sqrt(2.0 / (double)S) * cos(M_PI * ((double)n + 0.5) * (double)k / (double)S);
    if (k == 0) v *= 1.0 / sqrt(2.0);
    g_C[t] = (float)v;
}

// folded table sC[k*32 + n'] = C[k][n'], n' < 32
__device__ __forceinline__ void load_Cfold(float* sC, int t) {
    for (int i = t; i < M * 32; i += 256)
        sC[i] = g_C[(i >> 5) * S + (i & 31)];
}

// ---------------- K1: contract X (64 -> 16), float4 streaming -----------
// grid 1024 = 256 bi x 4 chunks of 1024 yz; thread owns 4 consecutive yz.
__global__ void __launch_bounds__(256) k1_fwd_x(const float* __restrict__ x) {
    __shared__ float sC[M * 32];
    const int t = threadIdx.x;
    const int bi = blockIdx.x >> 2;
    const int chunk = blockIdx.x & 3;
    load_Cfold(sC, t);
    __syncthreads();

    const int yz4 = chunk * 1024 + t * 4;
    const float* xp = x + (size_t)bi * (S * YZ) + yz4;

    float4 accE[8], accO[8];
    #pragma unroll
    for (int j = 0; j < 8; j++) {
        accE[j] = make_float4(0.f, 0.f, 0.f, 0.f);
        accO[j] = make_float4(0.f, 0.f, 0.f, 0.f);
    }

    #pragma unroll 4
    for (int Xp = 0; Xp < 32; Xp++) {
        float4 a = *(const float4*)(xp + (size_t)Xp * YZ);
        float4 b = *(const float4*)(xp + (size_t)(63 - Xp) * YZ);
        float4 e = make_float4(a.x + b.x, a.y + b.y, a.z + b.z, a.w + b.w);
        float4 o = make_float4(a.x - b.x, a.y - b.y, a.z - b.z, a.w - b.w);
        #pragma unroll
        for (int j = 0; j < 8; j++) {
            float cE = sC[(2 * j) * 32 + Xp];
            float cO = sC[(2 * j + 1) * 32 + Xp];
            accE[j].x += e.x * cE; accE[j].y += e.y * cE;
            accE[j].z += e.z * cE; accE[j].w += e.w * cE;
            accO[j].x += o.x * cO; accO[j].y += o.y * cO;
            accO[j].z += o.z * cO; accO[j].w += o.w * cO;
        }
    }
    float* gp = g_big + (size_t)bi * (M * YZ) + yz4;
    #pragma unroll
    for (int j = 0; j < 8; j++) {
        *(float4*)(gp + (size_t)(2 * j) * YZ) = accE[j];
        *(float4*)(gp + (size_t)(2 * j + 1) * YZ) = accO[j];
    }
}

// ---------------- K2: contract y then z, per (bi, 4 kx) -----------------
// grid 1024 = 256 bi x 4 kx-groups
__global__ void __launch_bounds__(256) k2_fwd_yz() {
    __shared__ float sC[M * 32];
    __shared__ float st[4 * M * S];   // [kxo][ky][z] 16 KB
    const int t = threadIdx.x;
    const int bi = blockIdx.x >> 2;
    const int kxg = blockIdx.x & 3;
    load_Cfold(sC, t);
    __syncthreads();

    // stage A: contract y. thread = (z, kxo)
    {
        const int z = t & 63, kxo = t >> 6;
        const int kx = kxg * 4 + kxo;
        const float* gp = g_big + ((size_t)bi * M + kx) * YZ + z;
        float accE[8], accO[8];
        #pragma unroll
        for (int j = 0; j < 8; j++) { accE[j] = 0.f; accO[j] = 0.f; }
        #pragma unroll 4
        for (int yp = 0; yp < 32; yp++) {
            float a = gp[yp * S];
            float b = gp[(63 - yp) * S];
            float e = a + b, o = a - b;
            #pragma unroll
            for (int j = 0; j < 8; j++) {
                accE[j] += e * sC[(2 * j) * 32 + yp];
                accO[j] += o * sC[(2 * j + 1) * 32 + yp];
            }
        }
        #pragma unroll
        for (int j = 0; j < 8; j++) {
            st[(kxo * M + 2 * j) * S + z] = accE[j];
            st[(kxo * M + 2 * j + 1) * S + z] = accO[j];
        }
    }
    __syncthreads();

    // stage B: contract z. thread = (kxo, ky, kz-quad)
    {
        const int kxo = t >> 6;
        const int ky = (t >> 2) & 15;
        const int kz0 = (t & 3) * 4;
        const int kx = kxg * 4 + kxo;
        const float* row = &st[(kxo * M + ky) * S];
        float4 acc = make_float4(0.f, 0.f, 0.f, 0.f);
        #pragma unroll 8
        for (int zp = 0; zp < 32; zp++) {
            float a = row[zp], b = row[63 - zp];
            float e = a + b, o = a - b;
            acc.x += e * sC[(kz0 + 0) * 32 + zp];
            acc.y += o * sC[(kz0 + 1) * 32 + zp];
            acc.z += e * sC[(kz0 + 2) * 32 + zp];
            acc.w += o * sC[(kz0 + 3) * 32 + zp];
        }
        *(float4*)(g_modes + (size_t)bi * MODES + kx * 256 + ky * M + kz0) = acc;
    }
}

// ---------------- K3: channel mix, batched register GEMM ----------------
__global__ void __launch_bounds__(256) k3_mix(const float* __restrict__ w) {
    __shared__ float s_m[8 * 32 * 16];   // [b][i][m] 16 KB
    __shared__ float s_w[32 * 16 * 16];  // [i][oo][m] 32 KB
    const int t = threadIdx.x;
    const int m0 = blockIdx.x * 16;
    const int o0 = blockIdx.y * 16;

    for (int idx = t; idx < 8 * 32 * 16; idx += 256) {
        int bi = idx >> 4, m = idx & 15;
        s_m[idx] = g_modes[(size_t)bi * MODES + m0 + m];
    }
    for (int idx = t; idx < 32 * 16 * 16; idx += 256) {
        int i = idx >> 8, oo = (idx >> 4) & 15, m = idx & 15;
        s_w[idx] = w[((size_t)i * 32 + o0 + oo) * MODES + m0 + m];
    }
    __syncthreads();

    const int oo = t >> 4;
    const int m = t & 15;
    float acc[8];
    #pragma unroll
    for (int b = 0; b < 8; b++) acc[b] = 0.f;
    #pragma unroll 8
    for (int i = 0; i < 32; i++) {
        float wv = s_w[(i * 16 + oo) * 16 + m];
        #pragma unroll
        for (int b = 0; b < 8; b++)
            acc[b] += s_m[(b * 32 + i) * 16 + m] * wv;
    }
    #pragma unroll
    for (int b = 0; b < 8; b++)
        g_mixed[((size_t)b * 32 + o0 + oo) * MODES + m0 + m] = acc[b];
}

// ---------------- K45: fused full inverse, per (bo, yp) -----------------
// Handles Y = yp and Y = 63-yp (y-fold). grid 8192 = 256 bo x 32 yp.
__global__ void __launch_bounds__(256) k45_inv(float* __restrict__ out) {
    __shared__ __align__(16) float s_m[MODES];   // 16 KB  [kx][ky][kz]
    __shared__ float sC[M * 32];                 // 2 KB
    __shared__ float s_tA[256];                  // [kx][kz] for Y=yp
    __shared__ float s_tB[256];                  // [kx][kz] for Y=63-yp
    __shared__ __align__(16) float s_vA[M * S];  // 4 KB [kx][Z]
    __shared__ __align__(16) float s_vB[M * S];  // 4 KB

    const int t = threadIdx.x;
    const int bo = blockIdx.x >> 5;
    const int yp = blockIdx.x & 31;

    {   // load modes (float4)
        const float4* src = (const float4*)(g_mixed + (size_t)bo * MODES);
        float4* dst = (float4*)s_m;
        #pragma unroll
        for (int i = t; i < MODES / 4; i += 256) dst[i] = src[i];
    }
    load_Cfold(sC, t);
    __syncthreads();

    // stage1: expand ky -> Y (fold): tmp[kx][kz] for both Y rows
    {
        const int kx = t >> 4, kz = t & 15;
        float e = 0.f, o = 0.f;
        #pragma unroll
        for (int j = 0; j < 8; j++) {
            e += sC[(2 * j) * 32 + yp] * s_m[kx * 256 + (2 * j) * M + kz];
            o += sC[(2 * j + 1) * 32 + yp] * s_m[kx * 256 + (2 * j + 1) * M + kz];
        }
        s_tA[t] = e + o;      // Y = yp
        s_tB[t] = e - o;      // Y = 63 - yp
    }
    __syncthreads();

    // stage2: expand kz -> Z (fold): v[kx][Z], 512 (kx,zp) slots, 2/thread
    #pragma unroll
    for (int it = 0; it < 2; it++) {
        int sidx = t + 256 * it;
        int zp = sidx & 31, kx = sidx >> 5;
        float eA = 0.f, oA = 0.f, eB = 0.f, oB = 0.f;
        #pragma unroll
        for (int j = 0; j < 8; j++) {
            float cE = sC[(2 * j) * 32 + zp];
            float cO = sC[(2 * j + 1) * 32 + zp];
            eA += cE * s_tA[kx * M + 2 * j];
            oA += cO * s_tA[kx * M + 2 * j + 1];
            eB += cE * s_tB[kx * M + 2 * j];
            oB += cO * s_tB[kx * M + 2 * j + 1];
        }
        s_vA[kx * S + zp] = eA + oA;
        s_vA[kx * S + 63 - zp] = eA - oA;
        s_vB[kx * S + zp] = eB + oB;
        s_vB[kx * S + 63 - zp] = eB - oB;
    }
    __syncthreads();

    // stage3: expand kx -> X (fold), register-cached v rows.
    // thread = (var = t>>7, xg = (t>>4)&7, zq = t&15); Xp = xg + 8i, i<4.
    {
        const int var = t >> 7;
        const int xg = (t >> 4) & 7;
        const int zq = t & 15;
        const float* v = var ? s_vB : s_vA;
        const int Y = var ? (63 - yp) : yp;

        float4 vE[8], vO[8];
        #pragma unroll
        for (int j = 0; j < 8; j++) {
            vE[j] = *(const float4*)(v + (2 * j) * S + zq * 4);
            vO[j] = *(const float4*)(v + (2 * j + 1) * S + zq * 4);
        }

        float* obase = out + (size_t)bo * (S * YZ) + Y * S + zq * 4;
        #pragma unroll
        for (int i = 0; i < 4; i++) {
            const int Xp = xg + 8 * i;
            float4 e = make_float4(0.f, 0.f, 0.f, 0.f);
            float4 o = make_float4(0.f, 0.f, 0.f, 0.f);
            #pragma unroll
            for (int j = 0; j < 8; j++) {
                float cE = sC[(2 * j) * 32 + Xp];
                float cO = sC[(2 * j + 1) * 32 + Xp];
                e.x += cE * vE[j].x; e.y += cE * vE[j].y;
                e.z += cE * vE[j].z; e.w += cE * vE[j].w;
                o.x += cO * vO[j].x; o.y += cO * vO[j].y;
                o.z += cO * vO[j].z; o.w += cO * vO[j].w;
            }
            *(float4*)(obase + (size_t)Xp * YZ) =
                make_float4(e.x + o.x, e.y + o.y, e.z + o.z, e.w + o.w);
            *(float4*)(obase + (size_t)(63 - Xp) * YZ) =
                make_float4(e.x - o.x, e.y - o.y, e.z - o.z, e.w - o.w);
        }
    }
}

// ---------------- launch ------------------------------------------------
extern "C" void kernel_launch(void* const* d_in, const int* in_sizes, int n_in,
                              void* d_out, int out_size) {
    const float* x = (const float*)d_in[0];
    const float* w = (const float*)d_in[1];
    if (n_in >= 2 && in_sizes[0] == 32 * 32 * MODES) {   // defensive swap
        x = (const float*)d_in[1];
        w = (const float*)d_in[0];
    }
    float* out = (float*)d_out;

    k0_init<<<1, 1024>>>();
    k1_fwd_x<<<1024, 256>>>(x);
    k2_fwd_yz<<<1024, 256>>>();
    k3_mix<<<dim3(256, 2), 256>>>(w);
    k45_inv<<<8192, 256>>>(out);
}